// round 2
// baseline (speedup 1.0000x reference)
#include <cuda_runtime.h>
#include <cuda_fp16.h>
#include <cstdint>

// Problem dims
#define BATCH 512
#define GK    4096     // IN
#define GN    11008    // OUT
#define GM    BATCH

// GEMM tiles
#define BM  128
#define BN  128
#define BK  32
#define PAD 8
#define LDS_K (BK + PAD)   // 40 halves per row -> 80B stride, conflict-free ldmatrix

// Scratch (allocation-free rule: __device__ globals)
__device__ __half g_w[(size_t)GN * GK];   // decompressed fp16 weights, ~90MB
__device__ __half g_x[(size_t)GM * GK];   // fp16 x, 4MB

// ---------------------------------------------------------------------------
// Kernel 1: QINS decompress via 256-entry LUT (no per-element exp).
// w = sign * exp(log_min + (255-stored)/254 * (log_max-log_min))
// sign in {-1,+1} -> XOR of fp16 sign bit.
// ---------------------------------------------------------------------------
__global__ void k_decompress(const int* __restrict__ stored,
                             const int* __restrict__ sign,
                             const float* __restrict__ lmin_p,
                             const float* __restrict__ lmax_p) {
    __shared__ unsigned short lut[256];
    float lmin = *lmin_p;
    float lrange = *lmax_p - lmin;
    for (int i = threadIdx.x; i < 256; i += blockDim.x) {
        float lw = lmin + ((255.0f - (float)i) * (1.0f / 254.0f)) * lrange;
        lut[i] = __half_as_ushort(__float2half_rn(__expf(lw)));
    }
    __syncthreads();

    const int4* s4 = (const int4*)stored;
    const int4* g4 = (const int4*)sign;
    uint4* w4 = (uint4*)g_w;

    const long long n8 = (long long)GN * GK / 8;  // 5,636,096
    long long i = (long long)blockIdx.x * blockDim.x + threadIdx.x;
    const long long stride = (long long)gridDim.x * blockDim.x;

    for (; i < n8; i += stride) {
        int4 sa = s4[2 * i], sb = s4[2 * i + 1];
        int4 ga = g4[2 * i], gb = g4[2 * i + 1];
        unsigned int h0 = lut[sa.x] ^ ((((unsigned)ga.x) >> 16) & 0x8000u);
        unsigned int h1 = lut[sa.y] ^ ((((unsigned)ga.y) >> 16) & 0x8000u);
        unsigned int h2 = lut[sa.z] ^ ((((unsigned)ga.z) >> 16) & 0x8000u);
        unsigned int h3 = lut[sa.w] ^ ((((unsigned)ga.w) >> 16) & 0x8000u);
        unsigned int h4 = lut[sb.x] ^ ((((unsigned)gb.x) >> 16) & 0x8000u);
        unsigned int h5 = lut[sb.y] ^ ((((unsigned)gb.y) >> 16) & 0x8000u);
        unsigned int h6 = lut[sb.z] ^ ((((unsigned)gb.z) >> 16) & 0x8000u);
        unsigned int h7 = lut[sb.w] ^ ((((unsigned)gb.w) >> 16) & 0x8000u);
        uint4 o;
        o.x = h0 | (h1 << 16);
        o.y = h2 | (h3 << 16);
        o.z = h4 | (h5 << 16);
        o.w = h6 | (h7 << 16);
        w4[i] = o;
    }
}

// ---------------------------------------------------------------------------
// Kernel 2: x fp32 -> fp16
// ---------------------------------------------------------------------------
__global__ void k_convert_x(const float* __restrict__ x) {
    const int n4 = GM * GK / 4;  // 524288
    uint2* xo = (uint2*)g_x;
    const float4* xi = (const float4*)x;
    for (int i = blockIdx.x * blockDim.x + threadIdx.x; i < n4;
         i += gridDim.x * blockDim.x) {
        float4 v = xi[i];
        __half2 a = __floats2half2_rn(v.x, v.y);
        __half2 b = __floats2half2_rn(v.z, v.w);
        uint2 o;
        o.x = *(unsigned int*)&a;
        o.y = *(unsigned int*)&b;
        xo[i] = o;
    }
}

// ---------------------------------------------------------------------------
// Kernel 3: TN GEMM via mma.sync m16n8k16 f16->f32.
// C[m=batch, n=out] = Xh[m,k] * Wh[n,k]^T ; epilogue (+bias[n])*scale[n].
// CTA 128x128x32, 256 threads, warps 2(m) x 4(n), warp tile 64x32.
// 2-stage cp.async pipeline.
// ---------------------------------------------------------------------------
__device__ __forceinline__ void cp_async16(void* smem, const void* gmem) {
    unsigned int s = (unsigned int)__cvta_generic_to_shared(smem);
    asm volatile("cp.async.cg.shared.global [%0], [%1], 16;\n" ::"r"(s), "l"(gmem));
}
__device__ __forceinline__ unsigned int smem_u32(const void* p) {
    return (unsigned int)__cvta_generic_to_shared(p);
}

__global__ void __launch_bounds__(256, 2)
k_gemm(const float* __restrict__ scale, const float* __restrict__ bias,
       float* __restrict__ out) {
    __shared__ __half As[2][BM][LDS_K];
    __shared__ __half Bs[2][BN][LDS_K];

    const int tid = threadIdx.x;
    const int lane = tid & 31;
    const int warp = tid >> 5;
    const int wm = warp & 1;   // 0..1 over M
    const int wn = warp >> 1;  // 0..3 over N
    const int bm0 = blockIdx.y * BM;
    const int bn0 = blockIdx.x * BN;

    float acc[4][4][4];
#pragma unroll
    for (int a = 0; a < 4; a++)
#pragma unroll
        for (int b = 0; b < 4; b++)
#pragma unroll
            for (int c = 0; c < 4; c++) acc[a][b][c] = 0.f;

    const __half* gA = g_x + (size_t)bm0 * GK;
    const __half* gB = g_w + (size_t)bn0 * GK;

    // ld mapping: 512 16B-chunks per tile, 2 per thread
    auto load_stage = [&](int s, int kt) {
        const int kk = kt * BK;
#pragma unroll
        for (int c = tid; c < (BM * BK / 8); c += 256) {
            int row = c >> 2;
            int col = (c & 3) * 8;
            cp_async16(&As[s][row][col], gA + (size_t)row * GK + kk + col);
            cp_async16(&Bs[s][row][col], gB + (size_t)row * GK + kk + col);
        }
    };

    load_stage(0, 0);
    asm volatile("cp.async.commit_group;\n" ::: "memory");
    load_stage(1, 1);
    asm volatile("cp.async.commit_group;\n" ::: "memory");

    const int NK = GK / BK;  // 128
    const int arow = lane & 15;
    const int acol = (lane >> 4) * 8;

    for (int kt = 0; kt < NK; ++kt) {
        asm volatile("cp.async.wait_group 1;\n" ::: "memory");
        __syncthreads();
        const int s = kt & 1;

#pragma unroll
        for (int ks = 0; ks < 2; ++ks) {
            unsigned int afr[4][4];
            unsigned int bfr[4][2];
#pragma unroll
            for (int mi = 0; mi < 4; ++mi) {
                unsigned int addr =
                    smem_u32(&As[s][wm * 64 + mi * 16 + arow][ks * 16 + acol]);
                asm volatile(
                    "ldmatrix.sync.aligned.m8n8.x4.shared.b16 {%0,%1,%2,%3}, [%4];\n"
                    : "=r"(afr[mi][0]), "=r"(afr[mi][1]), "=r"(afr[mi][2]),
                      "=r"(afr[mi][3])
                    : "r"(addr));
            }
#pragma unroll
            for (int nj = 0; nj < 2; ++nj) {
                unsigned int q0, q1, q2, q3;
                unsigned int addr =
                    smem_u32(&Bs[s][wn * 32 + nj * 16 + arow][ks * 16 + acol]);
                asm volatile(
                    "ldmatrix.sync.aligned.m8n8.x4.shared.b16 {%0,%1,%2,%3}, [%4];\n"
                    : "=r"(q0), "=r"(q1), "=r"(q2), "=r"(q3)
                    : "r"(addr));
                bfr[nj * 2][0] = q0;
                bfr[nj * 2][1] = q2;
                bfr[nj * 2 + 1][0] = q1;
                bfr[nj * 2 + 1][1] = q3;
            }
#pragma unroll
            for (int mi = 0; mi < 4; ++mi)
#pragma unroll
                for (int nf = 0; nf < 4; ++nf) {
                    asm volatile(
                        "mma.sync.aligned.m16n8k16.row.col.f32.f16.f16.f32 "
                        "{%0,%1,%2,%3}, {%4,%5,%6,%7}, {%8,%9}, {%0,%1,%2,%3};\n"
                        : "+f"(acc[mi][nf][0]), "+f"(acc[mi][nf][1]),
                          "+f"(acc[mi][nf][2]), "+f"(acc[mi][nf][3])
                        : "r"(afr[mi][0]), "r"(afr[mi][1]), "r"(afr[mi][2]),
                          "r"(afr[mi][3]), "r"(bfr[nf][0]), "r"(bfr[nf][1]));
                }
        }
        __syncthreads();
        if (kt + 2 < NK) load_stage(s, kt + 2);
        asm volatile("cp.async.commit_group;\n" ::: "memory");
    }

    // epilogue: (acc + bias[n]) * scale[n]
    const int row = lane >> 2;
    const int col2 = (lane & 3) * 2;
#pragma unroll
    for (int mi = 0; mi < 4; ++mi) {
        int m0 = bm0 + wm * 64 + mi * 16 + row;
#pragma unroll
        for (int nf = 0; nf < 4; ++nf) {
            int n0 = bn0 + wn * 32 + nf * 8 + col2;
            float s0 = scale[n0], s1 = scale[n0 + 1];
            float b0 = bias[n0], b1 = bias[n0 + 1];
            out[(size_t)m0 * GN + n0]           = (acc[mi][nf][0] + b0) * s0;
            out[(size_t)m0 * GN + n0 + 1]       = (acc[mi][nf][1] + b1) * s1;
            out[(size_t)(m0 + 8) * GN + n0]     = (acc[mi][nf][2] + b0) * s0;
            out[(size_t)(m0 + 8) * GN + n0 + 1] = (acc[mi][nf][3] + b1) * s1;
        }
    }
}

// ---------------------------------------------------------------------------
extern "C" void kernel_launch(void* const* d_in, const int* in_sizes, int n_in,
                              void* d_out, int out_size) {
    const float* x      = (const float*)d_in[0];
    const int*   stored = (const int*)d_in[1];
    const int*   sign   = (const int*)d_in[2];
    const float* lmin   = (const float*)d_in[3];
    const float* lmax   = (const float*)d_in[4];
    const float* scale  = (const float*)d_in[5];
    const float* bias   = (const float*)d_in[6];
    float* out = (float*)d_out;

    k_decompress<<<2960, 256>>>(stored, sign, lmin, lmax);
    k_convert_x<<<1024, 256>>>(x);
    dim3 grid(GN / BN, GM / BM);  // (86, 4)
    k_gemm<<<grid, 256>>>(scale, bias, out);
}